// round 16
// baseline (speedup 1.0000x reference)
#include <cuda_runtime.h>
#include <cstdint>

// VQ-VAE time-series forward, fp32 semantics via packed f32x2.
// R16: THREE kernels, each at its optimal config.
//  A enc MLP : 512 thr, 16 warps, K split across 2 warp-sets (traffic-neutral),
//              8-row x 4-col micro-tile per warp (R10 geometry), partials
//              combined in smem. z_e -> __device__ scratch.
//  B LN+VQ   : 256 thr, EXACT R10 VQ (2 instances/thread, fp64 c2, identical
//              f32x2 chains) reading z_e from scratch, writing z_q in place.
//  C dec MLP : mirror of A, reads z_q scratch, writes recon.
// MLP k-split changes only the summation split point (~1e-7 on z_e; argmin
// margin ~30x). VQ arithmetic bit-identical to R10.

namespace {
constexpr int kB      = 16384;
constexpr int kM      = 64;
constexpr int kTD     = 512;
constexpr int kHid    = 128;
constexpr int kCDim   = 64;
constexpr int kTok    = 8;
constexpr int kThrMLP = 512;
constexpr int kThrVQ  = 256;
constexpr int kSmemMLP = (kM * kTD + kM * kHid + 128 * 128) * 4;  // 229376
constexpr int kSmemVQ  = (256 * 64 + 256) * 4;                   // 66560
}

__device__ float g_mid[(size_t)kB * kTD];   // z_e, then z_q in place

using ull = unsigned long long;

__device__ __forceinline__ ull dup2(float a) {
  ull r;
  asm("mov.b64 %0, {%1, %1};" : "=l"(r) : "f"(a));
  return r;
}
__device__ __forceinline__ void fma2(ull& d, ull a, ull b) {
  asm("fma.rn.f32x2 %0, %1, %2, %0;" : "+l"(d) : "l"(a), "l"(b));
}
__device__ __forceinline__ ull add2(ull a, ull b) {
  ull d;
  asm("add.rn.f32x2 %0, %1, %2;" : "=l"(d) : "l"(a), "l"(b));
  return d;
}
__device__ __forceinline__ float2 unpack2(ull v) {
  float2 f;
  asm("mov.b64 {%0, %1}, %2;" : "=f"(f.x), "=f"(f.y) : "l"(v));
  return f;
}

union F4U2 { float4 f; ulonglong2 u; };

// C[8rows,4cols] += A[rows, 64-k-slice] * B[64,128]; 8 rows x (2 f32x2)/thread.
// k sequential -> per-output chain structure identical to R10/R11.
__device__ __forceinline__ void gemm64(const float* __restrict__ sA, int lda,
                                       const float* __restrict__ sB,
                                       int r0, int c0, ull (&acc)[8][2])
{
  #pragma unroll 4
  for (int kk = 0; kk < 64; kk += 4) {
    float4 av[8];
    ulonglong2 bv[4];
    #pragma unroll
    for (int i = 0; i < 8; ++i)
      av[i] = *reinterpret_cast<const float4*>(sA + (r0 + i) * lda + kk);
    #pragma unroll
    for (int j = 0; j < 4; ++j)
      bv[j] = *reinterpret_cast<const ulonglong2*>(sB + (kk + j) * 128 + c0);
    #pragma unroll
    for (int k = 0; k < 4; ++k) {
      #pragma unroll
      for (int i = 0; i < 8; ++i) {
        const float a = reinterpret_cast<const float*>(&av[i])[k];
        const ull ad = dup2(a);
        fma2(acc[i][0], ad, bv[k].x);
        fma2(acc[i][1], ad, bv[k].y);
      }
    }
  }
}

// LayerNorm of a 64-float vector held as 16 float4 in registers.
__device__ __forceinline__ void ln64(F4U2 (&zf)[16]) {
  float mu = 0.f;
  #pragma unroll
  for (int j = 0; j < 16; ++j)
    mu += (zf[j].f.x + zf[j].f.y) + (zf[j].f.z + zf[j].f.w);
  mu *= (1.f / 64.f);
  float var = 0.f;
  #pragma unroll
  for (int j = 0; j < 16; ++j) {
    float dx = zf[j].f.x - mu, dy = zf[j].f.y - mu;
    float dz = zf[j].f.z - mu, dw = zf[j].f.w - mu;
    var += (dx * dx + dy * dy) + (dz * dz + dw * dw);
  }
  var *= (1.f / 64.f);
  const float rs = rsqrtf(var + 1e-5f);
  #pragma unroll
  for (int j = 0; j < 16; ++j) {
    zf[j].f.x = (zf[j].f.x - mu) * rs;
    zf[j].f.y = (zf[j].f.y - mu) * rs;
    zf[j].f.z = (zf[j].f.z - mu) * rs;
    zf[j].f.w = (zf[j].f.w - mu) * rs;
  }
}

// ===================== Kernel A: encoder MLP =====================
__global__ void __launch_bounds__(kThrMLP, 1)
enc_kernel(const float* __restrict__ x,
           const float* __restrict__ ew1, const float* __restrict__ eb1,
           const float* __restrict__ ew2, const float* __restrict__ eb2)
{
  extern __shared__ float smem[];
  float* sZ = smem;                 // [64][512]
  float* sH = sZ + kM * kTD;        // [64][128]
  float* sW = sH + kM * kHid;       // [128][128] weight tile / combine buffer

  const int tid  = threadIdx.x;
  const int b0   = blockIdx.x * kM;
  const int wid  = tid >> 5;
  const int kset = wid >> 3;        // 0: k-lower half, 1: k-upper half
  const int r0   = (wid & 7) * 8;
  const int c0   = (tid & 31) * 4;

  {  // X tile [64,512]
    const float4* src = reinterpret_cast<const float4*>(x + (size_t)b0 * kTD);
    float4* dst = reinterpret_cast<float4*>(sZ);
    #pragma unroll
    for (int i = 0; i < 16; ++i)
      dst[tid + i * kThrMLP] = src[tid + i * kThrMLP];
  }

  ull acc[8][2];

  // ---- GEMM1: h = relu(X @ enc_w1 + b1); each kset does half of each k-tile
  #pragma unroll
  for (int i = 0; i < 8; ++i) { acc[i][0] = 0ull; acc[i][1] = 0ull; }
  for (int kt = 0; kt < 4; ++kt) {
    __syncthreads();
    const float4* src = reinterpret_cast<const float4*>(ew1 + kt * 128 * kHid);
    float4* dst = reinterpret_cast<float4*>(sW);
    #pragma unroll
    for (int i = 0; i < 8; ++i)
      dst[tid + i * kThrMLP] = src[tid + i * kThrMLP];
    __syncthreads();
    gemm64(sZ + kt * 128 + kset * 64, kTD, sW + kset * 64 * kHid, r0, c0, acc);
  }
  __syncthreads();
  if (kset == 1) {                  // publish upper-half partials
    ull* p = reinterpret_cast<ull*>(sW);
    #pragma unroll
    for (int i = 0; i < 8; ++i) {
      const int base = ((r0 + i) * kHid + c0) >> 1;
      p[base] = acc[i][0];
      p[base + 1] = acc[i][1];
    }
  }
  __syncthreads();
  if (kset == 0) {
    #pragma unroll
    for (int i = 0; i < 8; ++i) {
      float4 w = *reinterpret_cast<const float4*>(sW + (r0 + i) * kHid + c0);
      float2 p0 = unpack2(acc[i][0]);
      float2 p1 = unpack2(acc[i][1]);
      sH[(r0 + i) * kHid + c0 + 0] = fmaxf((p0.x + w.x) + __ldg(&eb1[c0 + 0]), 0.f);
      sH[(r0 + i) * kHid + c0 + 1] = fmaxf((p0.y + w.y) + __ldg(&eb1[c0 + 1]), 0.f);
      sH[(r0 + i) * kHid + c0 + 2] = fmaxf((p1.x + w.z) + __ldg(&eb1[c0 + 2]), 0.f);
      sH[(r0 + i) * kHid + c0 + 3] = fmaxf((p1.y + w.w) + __ldg(&eb1[c0 + 3]), 0.f);
    }
  }

  // ---- GEMM2: z_e = h @ enc_w2 + b2 (4 N-chunks), K=128 split 64/64
  for (int nc = 0; nc < 4; ++nc) {
    const int n0 = nc * 128;
    __syncthreads();                // sH ready (first iter) / sW free
    #pragma unroll
    for (int i = 0; i < 8; ++i) {
      const int q = tid + i * kThrMLP;
      const int k = q >> 5, c4 = q & 31;
      reinterpret_cast<float4*>(sW)[q] =
          *reinterpret_cast<const float4*>(ew2 + (size_t)k * kTD + n0 + c4 * 4);
    }
    __syncthreads();
    #pragma unroll
    for (int i = 0; i < 8; ++i) { acc[i][0] = 0ull; acc[i][1] = 0ull; }
    gemm64(sH + kset * 64, kHid, sW + kset * 64 * kHid, r0, c0, acc);
    __syncthreads();
    if (kset == 1) {
      ull* p = reinterpret_cast<ull*>(sW);
      #pragma unroll
      for (int i = 0; i < 8; ++i) {
        const int base = ((r0 + i) * kHid + c0) >> 1;
        p[base] = acc[i][0];
        p[base + 1] = acc[i][1];
      }
    }
    __syncthreads();
    if (kset == 0) {
      #pragma unroll
      for (int i = 0; i < 8; ++i) {
        float4 w = *reinterpret_cast<const float4*>(sW + (r0 + i) * kHid + c0);
        float2 p0 = unpack2(acc[i][0]);
        float2 p1 = unpack2(acc[i][1]);
        float4 o;
        o.x = (p0.x + w.x) + __ldg(&eb2[n0 + c0 + 0]);
        o.y = (p0.y + w.y) + __ldg(&eb2[n0 + c0 + 1]);
        o.z = (p1.x + w.z) + __ldg(&eb2[n0 + c0 + 2]);
        o.w = (p1.y + w.w) + __ldg(&eb2[n0 + c0 + 3]);
        *reinterpret_cast<float4*>(g_mid + (size_t)(b0 + r0 + i) * kTD + n0 + c0) = o;
      }
    }
  }
}

// ===================== Kernel B: LN + VQ (exact R10 arithmetic) =====================
__global__ void __launch_bounds__(kThrVQ, 1)
vq_kernel(const float* __restrict__ cbk, float* __restrict__ out, long long out_size)
{
  extern __shared__ float smem[];
  float* sW  = smem;                // [256][64] codebook tile
  float* sC2 = sW + 256 * 64;       // [256]

  const int tid = threadIdx.x;
  const int b0  = blockIdx.x * kM;

  const int rowA = tid >> 3,        tokA = tid & 7;
  const int rowB = 32 + (tid >> 3), tokB = tid & 7;
  float* zpA = g_mid + (size_t)(b0 + rowA) * kTD + tokA * kCDim;
  float* zpB = g_mid + (size_t)(b0 + rowB) * kTD + tokB * kCDim;

  F4U2 zfA[16], zfB[16];
  #pragma unroll
  for (int j = 0; j < 16; ++j)
    zfA[j].f = __ldg(reinterpret_cast<const float4*>(zpA) + j);
  #pragma unroll
  for (int j = 0; j < 16; ++j)
    zfB[j].f = __ldg(reinterpret_cast<const float4*>(zpB) + j);
  ln64(zfA);
  ln64(zfB);

  float bestA = 3.402823466e38f, bestB = 3.402823466e38f;
  int bidxA = 0, bidxB = 0;
  for (int pass = 0; pass < 2; ++pass) {
    __syncthreads();
    {  // codebook tile: 256 codes x 64 (contiguous 64KB)
      const float4* src = reinterpret_cast<const float4*>(cbk + pass * 256 * kCDim);
      float4* dst = reinterpret_cast<float4*>(sW);
      #pragma unroll
      for (int i = 0; i < 16; ++i)
        dst[tid + i * kThrVQ] = src[tid + i * kThrVQ];
    }
    __syncthreads();
    {
      // ||c||^2 for code `tid`, fp64 accumulation (error ~4e-6)
      double s = 0.0;
      const float4* cr = reinterpret_cast<const float4*>(sW + tid * kCDim);
      #pragma unroll
      for (int j = 0; j < 16; ++j) {
        float4 v = cr[j];
        s += (double)v.x * v.x + (double)v.y * v.y +
             (double)v.z * v.z + (double)v.w * v.w;
      }
      sC2[tid] = (float)s;
    }
    __syncthreads();
    for (int c = 0; c < 256; ++c) {
      const ulonglong2* cr = reinterpret_cast<const ulonglong2*>(sW + c * kCDim);
      ull a0 = 0ull, a1 = 0ull, a2 = 0ull, a3 = 0ull;
      ull b0v = 0ull, b1v = 0ull, b2v = 0ull, b3v = 0ull;
      #pragma unroll
      for (int j = 0; j < 16; j += 2) {
        ulonglong2 ca = cr[j];        // warp-uniform broadcast LDS.128
        ulonglong2 cb2 = cr[j + 1];
        fma2(a0, zfA[j].u.x, ca.x);
        fma2(a1, zfA[j].u.y, ca.y);
        fma2(a2, zfA[j + 1].u.x, cb2.x);
        fma2(a3, zfA[j + 1].u.y, cb2.y);
        fma2(b0v, zfB[j].u.x, ca.x);
        fma2(b1v, zfB[j].u.y, ca.y);
        fma2(b2v, zfB[j + 1].u.x, cb2.x);
        fma2(b3v, zfB[j + 1].u.y, cb2.y);
      }
      const float c2v = sC2[c];
      const int g = pass * 256 + c;
      {
        ull t = add2(add2(a0, a1), add2(a2, a3));
        float2 d2 = unpack2(t);
        const float dist = fmaf(-2.f, d2.x + d2.y, c2v);
        if (dist < bestA) { bestA = dist; bidxA = g; }   // strict < == first-min
      }
      {
        ull t = add2(add2(b0v, b1v), add2(b2v, b3v));
        float2 d2 = unpack2(t);
        const float dist = fmaf(-2.f, d2.x + d2.y, c2v);
        if (dist < bestB) { bestB = dist; bidxB = g; }
      }
    }
  }

  // gather + straight-through; z_q in place in g_mid + out z_q + indices
  {
    const bool wZ = out_size >= 2LL * kB * kTD;
    const bool wI = out_size >= 2LL * kB * kTD + (long long)kB * kTok;
    #pragma unroll
    for (int inst = 0; inst < 2; ++inst) {
      const int row = inst ? rowB : rowA;
      const int tok = inst ? tokB : tokA;
      const int bidx = inst ? bidxB : bidxA;
      F4U2* zf = inst ? zfB : zfA;
      float* zp = inst ? zpB : zpA;
      const float4* cr = reinterpret_cast<const float4*>(cbk + bidx * kCDim);
      float* ozq = out + (size_t)kB * kTD + (size_t)(b0 + row) * kTD + tok * kCDim;
      #pragma unroll
      for (int j = 0; j < 16; ++j) {
        float4 cv = __ldg(&cr[j]);
        float4 zq;
        zq.x = zf[j].f.x + (cv.x - zf[j].f.x);
        zq.y = zf[j].f.y + (cv.y - zf[j].f.y);
        zq.z = zf[j].f.z + (cv.z - zf[j].f.z);
        zq.w = zf[j].f.w + (cv.w - zf[j].f.w);
        reinterpret_cast<float4*>(zp)[j] = zq;
        if (wZ) reinterpret_cast<float4*>(ozq)[j] = zq;
      }
      if (wI)
        out[(size_t)2 * kB * kTD + (size_t)(b0 + row) * kTok + tok] = (float)bidx;
    }
  }
}

// ===================== Kernel C: decoder MLP =====================
__global__ void __launch_bounds__(kThrMLP, 1)
dec_kernel(const float* __restrict__ dw1, const float* __restrict__ db1,
           const float* __restrict__ dw2, const float* __restrict__ db2,
           float* __restrict__ out)
{
  extern __shared__ float smem[];
  float* sZ = smem;                 // [64][512] z_q
  float* sH = sZ + kM * kTD;        // [64][128]
  float* sW = sH + kM * kHid;       // [128][128]

  const int tid  = threadIdx.x;
  const int b0   = blockIdx.x * kM;
  const int wid  = tid >> 5;
  const int kset = wid >> 3;
  const int r0   = (wid & 7) * 8;
  const int c0   = (tid & 31) * 4;

  {  // z_q tile
    const float4* src = reinterpret_cast<const float4*>(g_mid + (size_t)b0 * kTD);
    float4* dst = reinterpret_cast<float4*>(sZ);
    #pragma unroll
    for (int i = 0; i < 16; ++i)
      dst[tid + i * kThrMLP] = src[tid + i * kThrMLP];
  }

  ull acc[8][2];

  // ---- GEMM3: h2 = relu(z_q @ dec_w1 + b1)
  #pragma unroll
  for (int i = 0; i < 8; ++i) { acc[i][0] = 0ull; acc[i][1] = 0ull; }
  for (int kt = 0; kt < 4; ++kt) {
    __syncthreads();
    const float4* src = reinterpret_cast<const float4*>(dw1 + kt * 128 * kHid);
    float4* dst = reinterpret_cast<float4*>(sW);
    #pragma unroll
    for (int i = 0; i < 8; ++i)
      dst[tid + i * kThrMLP] = src[tid + i * kThrMLP];
    __syncthreads();
    gemm64(sZ + kt * 128 + kset * 64, kTD, sW + kset * 64 * kHid, r0, c0, acc);
  }
  __syncthreads();
  if (kset == 1) {
    ull* p = reinterpret_cast<ull*>(sW);
    #pragma unroll
    for (int i = 0; i < 8; ++i) {
      const int base = ((r0 + i) * kHid + c0) >> 1;
      p[base] = acc[i][0];
      p[base + 1] = acc[i][1];
    }
  }
  __syncthreads();
  if (kset == 0) {
    #pragma unroll
    for (int i = 0; i < 8; ++i) {
      float4 w = *reinterpret_cast<const float4*>(sW + (r0 + i) * kHid + c0);
      float2 p0 = unpack2(acc[i][0]);
      float2 p1 = unpack2(acc[i][1]);
      sH[(r0 + i) * kHid + c0 + 0] = fmaxf((p0.x + w.x) + __ldg(&db1[c0 + 0]), 0.f);
      sH[(r0 + i) * kHid + c0 + 1] = fmaxf((p0.y + w.y) + __ldg(&db1[c0 + 1]), 0.f);
      sH[(r0 + i) * kHid + c0 + 2] = fmaxf((p1.x + w.z) + __ldg(&db1[c0 + 2]), 0.f);
      sH[(r0 + i) * kHid + c0 + 3] = fmaxf((p1.y + w.w) + __ldg(&db1[c0 + 3]), 0.f);
    }
  }

  // ---- GEMM4: recon = h2 @ dec_w2 + b2 -> gmem
  for (int nc = 0; nc < 4; ++nc) {
    const int n0 = nc * 128;
    __syncthreads();
    #pragma unroll
    for (int i = 0; i < 8; ++i) {
      const int q = tid + i * kThrMLP;
      const int k = q >> 5, c4 = q & 31;
      reinterpret_cast<float4*>(sW)[q] =
          *reinterpret_cast<const float4*>(dw2 + (size_t)k * kTD + n0 + c4 * 4);
    }
    __syncthreads();
    #pragma unroll
    for (int i = 0; i < 8; ++i) { acc[i][0] = 0ull; acc[i][1] = 0ull; }
    gemm64(sH + kset * 64, kHid, sW + kset * 64 * kHid, r0, c0, acc);
    __syncthreads();
    if (kset == 1) {
      ull* p = reinterpret_cast<ull*>(sW);
      #pragma unroll
      for (int i = 0; i < 8; ++i) {
        const int base = ((r0 + i) * kHid + c0) >> 1;
        p[base] = acc[i][0];
        p[base + 1] = acc[i][1];
      }
    }
    __syncthreads();
    if (kset == 0) {
      #pragma unroll
      for (int i = 0; i < 8; ++i) {
        float4 w = *reinterpret_cast<const float4*>(sW + (r0 + i) * kHid + c0);
        float2 p0 = unpack2(acc[i][0]);
        float2 p1 = unpack2(acc[i][1]);
        float4 o;
        o.x = (p0.x + w.x) + __ldg(&db2[n0 + c0 + 0]);
        o.y = (p0.y + w.y) + __ldg(&db2[n0 + c0 + 1]);
        o.z = (p1.x + w.z) + __ldg(&db2[n0 + c0 + 2]);
        o.w = (p1.y + w.w) + __ldg(&db2[n0 + c0 + 3]);
        *reinterpret_cast<float4*>(out + (size_t)(b0 + r0 + i) * kTD + n0 + c0) = o;
      }
    }
  }
}

extern "C" void kernel_launch(void* const* d_in, const int* in_sizes, int n_in,
                              void* d_out, int out_size)
{
  const float* x   = (const float*)d_in[0];
  const float* ew1 = (const float*)d_in[1];
  const float* eb1 = (const float*)d_in[2];
  const float* ew2 = (const float*)d_in[3];
  const float* eb2 = (const float*)d_in[4];
  const float* cbk = (const float*)d_in[5];
  const float* dw1 = (const float*)d_in[6];
  const float* db1 = (const float*)d_in[7];
  const float* dw2 = (const float*)d_in[8];
  const float* db2 = (const float*)d_in[9];

  cudaFuncSetAttribute(enc_kernel,
                       cudaFuncAttributeMaxDynamicSharedMemorySize, kSmemMLP);
  cudaFuncSetAttribute(vq_kernel,
                       cudaFuncAttributeMaxDynamicSharedMemorySize, kSmemVQ);
  cudaFuncSetAttribute(dec_kernel,
                       cudaFuncAttributeMaxDynamicSharedMemorySize, kSmemMLP);

  enc_kernel<<<kB / kM, kThrMLP, kSmemMLP>>>(x, ew1, eb1, ew2, eb2);
  vq_kernel<<<kB / kM, kThrVQ, kSmemVQ>>>(cbk, (float*)d_out, (long long)out_size);
  dec_kernel<<<kB / kM, kThrMLP, kSmemMLP>>>(dw1, db1, dw2, db2, (float*)d_out);
}

// round 17
// speedup vs baseline: 1.0035x; 1.0035x over previous
#include <cuda_runtime.h>
#include <cstdint>

// VQ-VAE forward. R17: VQ on tensor cores (mma.sync m16n8k8 tf32, 4xTF32
// exact-split), enc/dec MLP kernels verbatim from R16 (passed @4.67e-7).
//  A enc MLP : scalar f32x2, 512 thr (R16).
//  B VQ      : LN (exact scalar) -> z split hi/lo(tf32) in smem -> 4xTF32
//              mma over [256 tok x 512 codes x 64] -> strict first-min
//              argmin (in-thread ascending scan + quad bfly reduce with
//              index tie-break) -> z_q/indices epilogue.
//  C dec MLP : scalar f32x2 (R16).

namespace {
constexpr int kB      = 16384;
constexpr int kM      = 64;
constexpr int kTD     = 512;
constexpr int kHid    = 128;
constexpr int kCDim   = 64;
constexpr int kTok    = 8;
constexpr int kThrMLP = 512;
constexpr int kSmemMLP = (kM * kTD + kM * kHid + 128 * 128) * 4;  // 229376
// VQ kernel: 32 batch rows -> 256 tokens per CTA
constexpr int kMV     = 32;
constexpr int kThrVQ  = 256;
constexpr int kAPad   = 68;  // padded row stride (conflict-free frag loads)
constexpr int kSmemVQ = (2 * 256 * kAPad + 2 * 64 * kAPad + 512 + 256) * 4; // 177152
}

__device__ float g_mid[(size_t)kB * kTD];   // z_e, then z_q in place

using ull = unsigned long long;

__device__ __forceinline__ ull dup2(float a) {
  ull r;
  asm("mov.b64 %0, {%1, %1};" : "=l"(r) : "f"(a));
  return r;
}
__device__ __forceinline__ void fma2(ull& d, ull a, ull b) {
  asm("fma.rn.f32x2 %0, %1, %2, %0;" : "+l"(d) : "l"(a), "l"(b));
}
__device__ __forceinline__ float2 unpack2(ull v) {
  float2 f;
  asm("mov.b64 {%0, %1}, %2;" : "=f"(f.x), "=f"(f.y) : "l"(v));
  return f;
}
__device__ __forceinline__ uint32_t f2tf32(float x) {
  uint32_t r;
  asm("cvt.rna.tf32.f32 %0, %1;" : "=r"(r) : "f"(x));
  return r;
}
__device__ __forceinline__ void mma_tf32(float (&d)[4], const uint32_t (&a)[4],
                                         const uint32_t (&b)[2]) {
  asm("mma.sync.aligned.m16n8k8.row.col.f32.tf32.tf32.f32 "
      "{%0,%1,%2,%3}, {%4,%5,%6,%7}, {%8,%9}, {%0,%1,%2,%3};"
      : "+f"(d[0]), "+f"(d[1]), "+f"(d[2]), "+f"(d[3])
      : "r"(a[0]), "r"(a[1]), "r"(a[2]), "r"(a[3]), "r"(b[0]), "r"(b[1]));
}

union F4U2 { float4 f; ulonglong2 u; };

// C[8rows,4cols] += A * B over a 64-k slice; 8 rows x (2 f32x2)/thread. (R16)
__device__ __forceinline__ void gemm64(const float* __restrict__ sA, int lda,
                                       const float* __restrict__ sB,
                                       int r0, int c0, ull (&acc)[8][2])
{
  #pragma unroll 4
  for (int kk = 0; kk < 64; kk += 4) {
    float4 av[8];
    ulonglong2 bv[4];
    #pragma unroll
    for (int i = 0; i < 8; ++i)
      av[i] = *reinterpret_cast<const float4*>(sA + (r0 + i) * lda + kk);
    #pragma unroll
    for (int j = 0; j < 4; ++j)
      bv[j] = *reinterpret_cast<const ulonglong2*>(sB + (kk + j) * 128 + c0);
    #pragma unroll
    for (int k = 0; k < 4; ++k) {
      #pragma unroll
      for (int i = 0; i < 8; ++i) {
        const float a = reinterpret_cast<const float*>(&av[i])[k];
        const ull ad = dup2(a);
        fma2(acc[i][0], ad, bv[k].x);
        fma2(acc[i][1], ad, bv[k].y);
      }
    }
  }
}

__device__ __forceinline__ void ln64(F4U2 (&zf)[16]) {
  float mu = 0.f;
  #pragma unroll
  for (int j = 0; j < 16; ++j)
    mu += (zf[j].f.x + zf[j].f.y) + (zf[j].f.z + zf[j].f.w);
  mu *= (1.f / 64.f);
  float var = 0.f;
  #pragma unroll
  for (int j = 0; j < 16; ++j) {
    float dx = zf[j].f.x - mu, dy = zf[j].f.y - mu;
    float dz = zf[j].f.z - mu, dw = zf[j].f.w - mu;
    var += (dx * dx + dy * dy) + (dz * dz + dw * dw);
  }
  var *= (1.f / 64.f);
  const float rs = rsqrtf(var + 1e-5f);
  #pragma unroll
  for (int j = 0; j < 16; ++j) {
    zf[j].f.x = (zf[j].f.x - mu) * rs;
    zf[j].f.y = (zf[j].f.y - mu) * rs;
    zf[j].f.z = (zf[j].f.z - mu) * rs;
    zf[j].f.w = (zf[j].f.w - mu) * rs;
  }
}

// ===================== Kernel A: encoder MLP (R16 verbatim) =====================
__global__ void __launch_bounds__(kThrMLP, 1)
enc_kernel(const float* __restrict__ x,
           const float* __restrict__ ew1, const float* __restrict__ eb1,
           const float* __restrict__ ew2, const float* __restrict__ eb2)
{
  extern __shared__ float smem[];
  float* sZ = smem;
  float* sH = sZ + kM * kTD;
  float* sW = sH + kM * kHid;

  const int tid  = threadIdx.x;
  const int b0   = blockIdx.x * kM;
  const int wid  = tid >> 5;
  const int kset = wid >> 3;
  const int r0   = (wid & 7) * 8;
  const int c0   = (tid & 31) * 4;

  {
    const float4* src = reinterpret_cast<const float4*>(x + (size_t)b0 * kTD);
    float4* dst = reinterpret_cast<float4*>(sZ);
    #pragma unroll
    for (int i = 0; i < 16; ++i)
      dst[tid + i * kThrMLP] = src[tid + i * kThrMLP];
  }

  ull acc[8][2];

  #pragma unroll
  for (int i = 0; i < 8; ++i) { acc[i][0] = 0ull; acc[i][1] = 0ull; }
  for (int kt = 0; kt < 4; ++kt) {
    __syncthreads();
    const float4* src = reinterpret_cast<const float4*>(ew1 + kt * 128 * kHid);
    float4* dst = reinterpret_cast<float4*>(sW);
    #pragma unroll
    for (int i = 0; i < 8; ++i)
      dst[tid + i * kThrMLP] = src[tid + i * kThrMLP];
    __syncthreads();
    gemm64(sZ + kt * 128 + kset * 64, kTD, sW + kset * 64 * kHid, r0, c0, acc);
  }
  __syncthreads();
  if (kset == 1) {
    ull* p = reinterpret_cast<ull*>(sW);
    #pragma unroll
    for (int i = 0; i < 8; ++i) {
      const int base = ((r0 + i) * kHid + c0) >> 1;
      p[base] = acc[i][0];
      p[base + 1] = acc[i][1];
    }
  }
  __syncthreads();
  if (kset == 0) {
    #pragma unroll
    for (int i = 0; i < 8; ++i) {
      float4 w = *reinterpret_cast<const float4*>(sW + (r0 + i) * kHid + c0);
      float2 p0 = unpack2(acc[i][0]);
      float2 p1 = unpack2(acc[i][1]);
      sH[(r0 + i) * kHid + c0 + 0] = fmaxf((p0.x + w.x) + __ldg(&eb1[c0 + 0]), 0.f);
      sH[(r0 + i) * kHid + c0 + 1] = fmaxf((p0.y + w.y) + __ldg(&eb1[c0 + 1]), 0.f);
      sH[(r0 + i) * kHid + c0 + 2] = fmaxf((p1.x + w.z) + __ldg(&eb1[c0 + 2]), 0.f);
      sH[(r0 + i) * kHid + c0 + 3] = fmaxf((p1.y + w.w) + __ldg(&eb1[c0 + 3]), 0.f);
    }
  }

  for (int nc = 0; nc < 4; ++nc) {
    const int n0 = nc * 128;
    __syncthreads();
    #pragma unroll
    for (int i = 0; i < 8; ++i) {
      const int q = tid + i * kThrMLP;
      const int k = q >> 5, c4 = q & 31;
      reinterpret_cast<float4*>(sW)[q] =
          *reinterpret_cast<const float4*>(ew2 + (size_t)k * kTD + n0 + c4 * 4);
    }
    __syncthreads();
    #pragma unroll
    for (int i = 0; i < 8; ++i) { acc[i][0] = 0ull; acc[i][1] = 0ull; }
    gemm64(sH + kset * 64, kHid, sW + kset * 64 * kHid, r0, c0, acc);
    __syncthreads();
    if (kset == 1) {
      ull* p = reinterpret_cast<ull*>(sW);
      #pragma unroll
      for (int i = 0; i < 8; ++i) {
        const int base = ((r0 + i) * kHid + c0) >> 1;
        p[base] = acc[i][0];
        p[base + 1] = acc[i][1];
      }
    }
    __syncthreads();
    if (kset == 0) {
      #pragma unroll
      for (int i = 0; i < 8; ++i) {
        float4 w = *reinterpret_cast<const float4*>(sW + (r0 + i) * kHid + c0);
        float2 p0 = unpack2(acc[i][0]);
        float2 p1 = unpack2(acc[i][1]);
        float4 o;
        o.x = (p0.x + w.x) + __ldg(&eb2[n0 + c0 + 0]);
        o.y = (p0.y + w.y) + __ldg(&eb2[n0 + c0 + 1]);
        o.z = (p1.x + w.z) + __ldg(&eb2[n0 + c0 + 2]);
        o.w = (p1.y + w.w) + __ldg(&eb2[n0 + c0 + 3]);
        *reinterpret_cast<float4*>(g_mid + (size_t)(b0 + r0 + i) * kTD + n0 + c0) = o;
      }
    }
  }
}

// ===================== Kernel B: LN + VQ via tf32 mma (4xTF32) =====================
__global__ void __launch_bounds__(kThrVQ, 1)
vq_mma_kernel(const float* __restrict__ cbk, float* __restrict__ out,
              long long out_size)
{
  extern __shared__ float smem[];
  float* sAhi = smem;                       // [256][68] normalized z hi
  float* sAlo = sAhi + 256 * kAPad;         // [256][68] lo
  float* sBhi = sAlo + 256 * kAPad;         // [64][68] code block hi
  float* sBlo = sBhi + 64 * kAPad;          // [64][68] lo
  float* sC2  = sBlo + 64 * kAPad;          // [512] fp64-accumulated ||c||^2
  int*   sIdx = reinterpret_cast<int*>(sC2 + 512);  // [256]

  const int tid  = threadIdx.x;
  const int b0   = blockIdx.x * kMV;
  const int row  = tid >> 3;                // local batch row 0..31
  const int tok  = tid & 7;
  const int lane = tid & 31;
  const int wid  = tid >> 5;
  const int qid  = lane >> 2;               // 0..7
  const int qtid = lane & 3;                // 0..3

  // ---- LN (exact, same arithmetic as R16) + tf32 split into smem ----
  {
    const float* zp = g_mid + (size_t)(b0 + row) * kTD + tok * kCDim;
    F4U2 zf[16];
    #pragma unroll
    for (int j = 0; j < 16; ++j)
      zf[j].f = __ldg(reinterpret_cast<const float4*>(zp) + j);
    ln64(zf);
    #pragma unroll
    for (int j = 0; j < 16; ++j) {
      const float* e = reinterpret_cast<const float*>(&zf[j].f);
      #pragma unroll
      for (int q = 0; q < 4; ++q) {
        const float xv = e[q];
        const uint32_t hb = f2tf32(xv);
        const float fh = __uint_as_float(hb);
        const uint32_t lb = f2tf32(xv - fh);
        sAhi[tid * kAPad + j * 4 + q] = fh;
        sAlo[tid * kAPad + j * 4 + q] = __uint_as_float(lb);
      }
    }
  }

  // ---- c2: fp64 accumulation, same formula as R10/R16 ----
  #pragma unroll
  for (int t2 = 0; t2 < 2; ++t2) {
    const int code = tid + t2 * 256;
    double s = 0.0;
    const float4* cr = reinterpret_cast<const float4*>(cbk + code * kCDim);
    #pragma unroll
    for (int j = 0; j < 16; ++j) {
      float4 v = __ldg(&cr[j]);
      s += (double)v.x * v.x + (double)v.y * v.y +
           (double)v.z * v.z + (double)v.w * v.w;
    }
    sC2[code] = (float)s;
  }

  // ---- mma scan: 8 code blocks of 64; 2 row-tiles of 16 tokens per warp ----
  float rd[2][2] = { {3.402823466e38f, 3.402823466e38f},
                     {3.402823466e38f, 3.402823466e38f} };
  int   ri[2][2] = { {0, 0}, {0, 0} };

  for (int blk = 0; blk < 8; ++blk) {
    __syncthreads();                        // prior readers of sB done; A/c2 ready
    #pragma unroll
    for (int u = 0; u < 16; ++u) {          // stage 64x64 code block, split hi/lo
      const int e = u * kThrVQ + tid;
      const int n = e >> 6, k = e & 63;
      const float xv = __ldg(cbk + (size_t)blk * 4096 + e);
      const uint32_t hb = f2tf32(xv);
      const float fh = __uint_as_float(hb);
      const uint32_t lb = f2tf32(xv - fh);
      sBhi[n * kAPad + k] = fh;
      sBlo[n * kAPad + k] = __uint_as_float(lb);
    }
    __syncthreads();

    #pragma unroll
    for (int rt2 = 0; rt2 < 2; ++rt2) {
      const int abase = (wid * 2 + rt2) * 16;
      float acc[8][4];
      #pragma unroll
      for (int nt = 0; nt < 8; ++nt)
        #pragma unroll
        for (int q = 0; q < 4; ++q) acc[nt][q] = 0.f;

      for (int ks = 0; ks < 8; ++ks) {
        const int r0 = abase + qid;
        const int k0 = ks * 8 + qtid;
        uint32_t ah[4], al[4];
        ah[0] = __float_as_uint(sAhi[r0 * kAPad + k0]);
        ah[1] = __float_as_uint(sAhi[(r0 + 8) * kAPad + k0]);
        ah[2] = __float_as_uint(sAhi[r0 * kAPad + k0 + 4]);
        ah[3] = __float_as_uint(sAhi[(r0 + 8) * kAPad + k0 + 4]);
        al[0] = __float_as_uint(sAlo[r0 * kAPad + k0]);
        al[1] = __float_as_uint(sAlo[(r0 + 8) * kAPad + k0]);
        al[2] = __float_as_uint(sAlo[r0 * kAPad + k0 + 4]);
        al[3] = __float_as_uint(sAlo[(r0 + 8) * kAPad + k0 + 4]);
        #pragma unroll
        for (int nt = 0; nt < 8; ++nt) {
          const int n0 = nt * 8 + qid;
          uint32_t bh[2], bl[2];
          bh[0] = __float_as_uint(sBhi[n0 * kAPad + k0]);
          bh[1] = __float_as_uint(sBhi[n0 * kAPad + k0 + 4]);
          bl[0] = __float_as_uint(sBlo[n0 * kAPad + k0]);
          bl[1] = __float_as_uint(sBlo[n0 * kAPad + k0 + 4]);
          mma_tf32(acc[nt], ah, bh);        // hi*hi
          mma_tf32(acc[nt], ah, bl);        // hi*lo
          mma_tf32(acc[nt], al, bh);        // lo*hi
          mma_tf32(acc[nt], al, bl);        // lo*lo
        }
      }
      // epilogue: dist = c2 - 2*dot; in-thread scan is ascending code index
      #pragma unroll
      for (int nt = 0; nt < 8; ++nt) {
        const int cb = blk * 64 + nt * 8 + 2 * qtid;
        float d;
        d = fmaf(-2.f, acc[nt][0], sC2[cb]);
        if (d < rd[rt2][0]) { rd[rt2][0] = d; ri[rt2][0] = cb; }
        d = fmaf(-2.f, acc[nt][1], sC2[cb + 1]);
        if (d < rd[rt2][0]) { rd[rt2][0] = d; ri[rt2][0] = cb + 1; }
        d = fmaf(-2.f, acc[nt][2], sC2[cb]);
        if (d < rd[rt2][1]) { rd[rt2][1] = d; ri[rt2][1] = cb; }
        d = fmaf(-2.f, acc[nt][3], sC2[cb + 1]);
        if (d < rd[rt2][1]) { rd[rt2][1] = d; ri[rt2][1] = cb + 1; }
      }
    }
  }

  // ---- quad reduce (cols spread over lane&3) with first-min tie-break ----
  #pragma unroll
  for (int rt2 = 0; rt2 < 2; ++rt2) {
    #pragma unroll
    for (int slot = 0; slot < 2; ++slot) {
      float d = rd[rt2][slot];
      int   i = ri[rt2][slot];
      #pragma unroll
      for (int off = 1; off <= 2; off <<= 1) {
        const float od = __shfl_xor_sync(0xffffffffu, d, off);
        const int   oi = __shfl_xor_sync(0xffffffffu, i, off);
        if (od < d || (od == d && oi < i)) { d = od; i = oi; }
      }
      if (qtid == 0)
        sIdx[(wid * 2 + rt2) * 16 + qid + slot * 8] = i;
    }
  }
  __syncthreads();

  // ---- gather + straight-through; z_q to g_mid + out; indices ----
  {
    const int bidx = sIdx[tid];
    const bool wZ = out_size >= 2LL * kB * kTD;
    const bool wI = out_size >= 2LL * kB * kTD + (long long)kB * kTok;
    float* zq_mid = g_mid + (size_t)(b0 + row) * kTD + tok * kCDim;
    float* ozq = out + (size_t)kB * kTD + (size_t)(b0 + row) * kTD + tok * kCDim;
    const float* cr = cbk + (size_t)bidx * kCDim;
    #pragma unroll
    for (int j = 0; j < 16; ++j) {
      float4 cv = __ldg(reinterpret_cast<const float4*>(cr) + j);
      float4 zt;
      zt.x = sAhi[tid * kAPad + j * 4 + 0] + sAlo[tid * kAPad + j * 4 + 0];
      zt.y = sAhi[tid * kAPad + j * 4 + 1] + sAlo[tid * kAPad + j * 4 + 1];
      zt.z = sAhi[tid * kAPad + j * 4 + 2] + sAlo[tid * kAPad + j * 4 + 2];
      zt.w = sAhi[tid * kAPad + j * 4 + 3] + sAlo[tid * kAPad + j * 4 + 3];
      float4 zq;
      zq.x = zt.x + (cv.x - zt.x);
      zq.y = zt.y + (cv.y - zt.y);
      zq.z = zt.z + (cv.z - zt.z);
      zq.w = zt.w + (cv.w - zt.w);
      reinterpret_cast<float4*>(zq_mid)[j] = zq;
      if (wZ) reinterpret_cast<float4*>(ozq)[j] = zq;
    }
    if (wI)
      out[(size_t)2 * kB * kTD + (size_t)(b0 + row) * kTok + tok] = (float)bidx;
  }
}

// ===================== Kernel C: decoder MLP (R16 verbatim) =====================
__global__ void __launch_bounds__(kThrMLP, 1)
dec_kernel(const float* __restrict__ dw1, const float* __restrict__ db1,
           const float* __restrict__ dw2, const float* __restrict__ db2,
           float* __restrict__ out)
{
  extern __shared__ float smem[];
  float* sZ = smem;
  float* sH = sZ + kM * kTD;
  float* sW = sH + kM * kHid;

  const int tid  = threadIdx.x;
  const int b0   = blockIdx.x * kM;
  const int wid  = tid >> 5;
  const int kset = wid >> 3;
  const int r0   = (wid & 7) * 8;
  const int c0   = (tid & 31) * 4;

  {
    const float4* src = reinterpret_cast<const float4*>(g_mid + (size_t)b0 * kTD);
    float4* dst = reinterpret_cast<float4*>(sZ);
    #pragma unroll
    for (int i = 0; i < 16; ++i)
      dst[tid + i * kThrMLP] = src[tid + i * kThrMLP];
  }

  ull acc[8][2];

  #pragma unroll
  for (int i = 0; i < 8; ++i) { acc[i][0] = 0ull; acc[i][1] = 0ull; }
  for (int kt = 0; kt < 4; ++kt) {
    __syncthreads();
    const float4* src = reinterpret_cast<const float4*>(dw1 + kt * 128 * kHid);
    float4* dst = reinterpret_cast<float4*>(sW);
    #pragma unroll
    for (int i = 0; i < 8; ++i)
      dst[tid + i * kThrMLP] = src[tid + i * kThrMLP];
    __syncthreads();
    gemm64(sZ + kt * 128 + kset * 64, kTD, sW + kset * 64 * kHid, r0, c0, acc);
  }
  __syncthreads();
  if (kset == 1) {
    ull* p = reinterpret_cast<ull*>(sW);
    #pragma unroll
    for (int i = 0; i < 8; ++i) {
      const int base = ((r0 + i) * kHid + c0) >> 1;
      p[base] = acc[i][0];
      p[base + 1] = acc[i][1];
    }
  }
  __syncthreads();
  if (kset == 0) {
    #pragma unroll
    for (int i = 0; i < 8; ++i) {
      float4 w = *reinterpret_cast<const float4*>(sW + (r0 + i) * kHid + c0);
      float2 p0 = unpack2(acc[i][0]);
      float2 p1 = unpack2(acc[i][1]);
      sH[(r0 + i) * kHid + c0 + 0] = fmaxf((p0.x + w.x) + __ldg(&db1[c0 + 0]), 0.f);
      sH[(r0 + i) * kHid + c0 + 1] = fmaxf((p0.y + w.y) + __ldg(&db1[c0 + 1]), 0.f);
      sH[(r0 + i) * kHid + c0 + 2] = fmaxf((p1.x + w.z) + __ldg(&db1[c0 + 2]), 0.f);
      sH[(r0 + i) * kHid + c0 + 3] = fmaxf((p1.y + w.w) + __ldg(&db1[c0 + 3]), 0.f);
    }
  }

  for (int nc = 0; nc < 4; ++nc) {
    const int n0 = nc * 128;
    __syncthreads();
    #pragma unroll
    for (int i = 0; i < 8; ++i) {
      const int q = tid + i * kThrMLP;
      const int k = q >> 5, c4 = q & 31;
      reinterpret_cast<float4*>(sW)[q] =
          *reinterpret_cast<const float4*>(dw2 + (size_t)k * kTD + n0 + c4 * 4);
    }
    __syncthreads();
    #pragma unroll
    for (int i = 0; i < 8; ++i) { acc[i][0] = 0ull; acc[i][1] = 0ull; }
    gemm64(sH + kset * 64, kHid, sW + kset * 64 * kHid, r0, c0, acc);
    __syncthreads();
    if (kset == 1) {
      ull* p = reinterpret_cast<ull*>(sW);
      #pragma unroll
      for (int i = 0; i < 8; ++i) {
        const int base = ((r0 + i) * kHid + c0) >> 1;
        p[base] = acc[i][0];
        p[base + 1] = acc[i][1];
      }
    }
    __syncthreads();
    if (kset == 0) {
      #pragma unroll
      for (int i = 0; i < 8; ++i) {
        float4 w = *reinterpret_cast<const float4*>(sW + (r0 + i) * kHid + c0);
        float2 p0 = unpack2(acc[i][0]);
        float2 p1 = unpack2(acc[i][1]);
        float4 o;
        o.x = (p0.x + w.x) + __ldg(&db2[n0 + c0 + 0]);
        o.y = (p0.y + w.y) + __ldg(&db2[n0 + c0 + 1]);
        o.z = (p1.x + w.z) + __ldg(&db2[n0 + c0 + 2]);
        o.w = (p1.y + w.w) + __ldg(&db2[n0 + c0 + 3]);
        *reinterpret_cast<float4*>(out + (size_t)(b0 + r0 + i) * kTD + n0 + c0) = o;
      }
    }
  }
}

extern "C" void kernel_launch(void* const* d_in, const int* in_sizes, int n_in,
                              void* d_out, int out_size)
{
  const float* x   = (const float*)d_in[0];
  const float* ew1 = (const float*)d_in[1];
  const float* eb1 = (const float*)d_in[2];
  const float* ew2 = (const float*)d_in[3];
  const float* eb2 = (const float*)d_in[4];
  const float* cbk = (const float*)d_in[5];
  const float* dw1 = (const float*)d_in[6];
  const float* db1 = (const float*)d_in[7];
  const float* dw2 = (const float*)d_in[8];
  const float* db2 = (const float*)d_in[9];

  cudaFuncSetAttribute(enc_kernel,
                       cudaFuncAttributeMaxDynamicSharedMemorySize, kSmemMLP);
  cudaFuncSetAttribute(vq_mma_kernel,
                       cudaFuncAttributeMaxDynamicSharedMemorySize, kSmemVQ);
  cudaFuncSetAttribute(dec_kernel,
                       cudaFuncAttributeMaxDynamicSharedMemorySize, kSmemMLP);

  enc_kernel<<<kB / kM, kThrMLP, kSmemMLP>>>(x, ew1, eb1, ew2, eb2);
  vq_mma_kernel<<<kB / kMV, kThrVQ, kSmemVQ>>>(cbk, (float*)d_out,
                                               (long long)out_size);
  dec_kernel<<<kB / kM, kThrMLP, kSmemMLP>>>(dw1, db1, dw2, db2, (float*)d_out);
}